// round 11
// baseline (speedup 1.0000x reference)
#include <cuda_runtime.h>
#include <math.h>
#include <stdint.h>

#define KC 4
#define D  8
#define NTRI 36   // lower-triangular 8x8 element count

#define LOG_2PI 1.8378770664093453f
#define LN2F    0.6931471805599453f

__device__ __forceinline__ float rcp_a(float x)  { float y; asm("rcp.approx.f32 %0, %1;"   : "=f"(y) : "f"(x)); return y; }
__device__ __forceinline__ float rsq_a(float x)  { float y; asm("rsqrt.approx.f32 %0, %1;" : "=f"(y) : "f"(x)); return y; }
__device__ __forceinline__ float lg2_a(float x)  { float y; asm("lg2.approx.f32 %0, %1;"   : "=f"(y) : "f"(x)); return y; }

// Hot-path params (0.5 folded: sL = Linv/sqrt2, nb = -bias/sqrt2, so
// lp = cf + sum_r (sL·x + nb)^2 directly).
struct HotP {
    float sL[KC][NTRI];
    float nb[KC][D];
    float cf[KC];
    int   active[KC];
    int   tmask[KC];
    int   emask[KC];
};

__device__ double g_sum = 0.0;   // reset by final_kernel each launch

// ---------------------------------------------------------------------------
// Per-thread component prep: Cholesky + triangular inverse + log-det (fp32,
// approx MUFU). Writes scaled params for component j into the given HotP.
// ---------------------------------------------------------------------------
__device__ __forceinline__ void prep_component(HotP* p, int j,
                                               const float* __restrict__ means,
                                               const float* __restrict__ covs)
{
    const float INV_SQRT2 = 0.70710678118654752f;
    float L[D][D], Li[D][D];
    const float* a = covs + j * D * D;
    #pragma unroll
    for (int r = 0; r < D; ++r) {
        #pragma unroll
        for (int c = 0; c <= r; ++c) {
            float s = a[r * D + c];
            #pragma unroll
            for (int k = 0; k < c; ++k) s -= L[r][k] * L[c][k];
            if (c == r) L[r][c] = s * rsq_a(s);
            else        L[r][c] = s * rcp_a(L[c][c]);
        }
    }
    float hld = 0.0f;
    #pragma unroll
    for (int c = 0; c < D; ++c) {
        Li[c][c] = rcp_a(L[c][c]);
        #pragma unroll
        for (int r = c + 1; r < D; ++r) {
            float s = 0.0f;
            #pragma unroll
            for (int k = c; k < r; ++k) s += L[r][k] * Li[k][c];
            Li[r][c] = -s * rcp_a(L[r][r]);
        }
        hld += lg2_a(L[c][c]);
    }
    hld *= LN2F;

    int t = 0;
    #pragma unroll
    for (int r = 0; r < D; ++r)
        #pragma unroll
        for (int c = 0; c <= r; ++c) {
            p->sL[j][t] = Li[r][c] * INV_SQRT2;
            ++t;
        }
    #pragma unroll
    for (int r = 0; r < D; ++r) {
        float s = 0.0f;
        #pragma unroll
        for (int c = 0; c <= r; ++c) s += Li[r][c] * means[j * D + c];
        p->nb[j][r] = -s * INV_SQRT2;
    }
    p->cf[j] = 0.5f * (float)D * LOG_2PI - hld;
}

__device__ __forceinline__ void prep_masks(HotP* p, const int* __restrict__ indices)
{
    for (int i = 0; i < KC; ++i) {
        int ci = indices[i];
        p->active[i] = (ci != 0);
        int ti = ci; if (ti < 0) ti = 0; if (ti > KC - 1) ti = KC - 1;
        p->tmask[i] = 1 << ti;
        int em = 0;
        for (int jj = 0; jj < KC; ++jj)
            if (indices[jj] == ci && jj != i) em |= (1 << jj);
        p->emask[i] = em;
    }
}

// ---------------------------------------------------------------------------
// Hot kernel: per-block inline setup (threads 0-3 -> shared, ~1us paid
// concurrently), then the PROVEN 63.5us R6 body, fp64 block reduce.
// ---------------------------------------------------------------------------
__global__ void __launch_bounds__(256) lp_kernel(const float* __restrict__ pred, int N,
                                                 const float* __restrict__ means,
                                                 const float* __restrict__ covs,
                                                 const int*   __restrict__ indices)
{
    __shared__ HotP sh;
    if (threadIdx.x < KC)
        prep_component(&sh, threadIdx.x, means, covs);
    if (threadIdx.x == 0)
        prep_masks(&sh, indices);
    __syncthreads();

    const int N4 = N >> 2;
    const int tid = blockIdx.x * blockDim.x + threadIdx.x;
    const int stride = gridDim.x * blockDim.x;

    float acc = 0.0f;

    for (int v = tid; v < N4; v += stride) {
        #pragma unroll
        for (int i = 0; i < KC; ++i) {
            if (!sh.active[i]) continue;
            const float4* base = (const float4*)pred + (size_t)i * D * N4;
            float4 x[D];
            #pragma unroll
            for (int dd = 0; dd < D; ++dd)
                x[dd] = base[(size_t)dd * N4 + v];

            float lp[KC][4];
            #pragma unroll
            for (int j = 0; j < KC; ++j) {
                float M0 = sh.cf[j], M1 = M0, M2 = M0, M3 = M0;
                int t = 0;
                #pragma unroll
                for (int r = 0; r < D; ++r) {
                    float nb = sh.nb[j][r];
                    float s0 = nb, s1 = nb, s2 = nb, s3 = nb;
                    #pragma unroll
                    for (int c = 0; c <= r; ++c) {
                        float l = sh.sL[j][t]; ++t;
                        s0 = fmaf(l, x[c].x, s0);
                        s1 = fmaf(l, x[c].y, s1);
                        s2 = fmaf(l, x[c].z, s2);
                        s3 = fmaf(l, x[c].w, s3);
                    }
                    M0 = fmaf(s0, s0, M0);
                    M1 = fmaf(s1, s1, M1);
                    M2 = fmaf(s2, s2, M2);
                    M3 = fmaf(s3, s3, M3);
                }
                lp[j][0] = M0; lp[j][1] = M1; lp[j][2] = M2; lp[j][3] = M3;
            }

            const int tm = sh.tmask[i];
            const int em = sh.emask[i];
            #pragma unroll
            for (int s = 0; s < 4; ++s) {
                float e0 = __expf(lp[0][s]);
                float e1 = __expf(lp[1][s]);
                float e2 = __expf(lp[2][s]);
                float e3 = __expf(lp[3][s]);
                float tot = 1e-8f + ((e0 + e1) + (e2 + e3));
                if (em) {
                    tot -= (em & 1) ? e0 : 0.0f;
                    tot -= (em & 2) ? e1 : 0.0f;
                    tot -= (em & 4) ? e2 : 0.0f;
                    tot -= (em & 8) ? e3 : 0.0f;
                }
                float tll = (tm & 1) ? lp[0][s]
                          : (tm & 2) ? lp[1][s]
                          : (tm & 4) ? lp[2][s] : lp[3][s];
                acc += tll - __logf(tot);
            }
        }
    }

    // fp64 block reduction
    double dacc = (double)acc;
    #pragma unroll
    for (int off = 16; off > 0; off >>= 1)
        dacc += __shfl_down_sync(0xffffffffu, dacc, off);
    __shared__ double wsum[8];
    int lane = threadIdx.x & 31;
    int w = threadIdx.x >> 5;
    if (lane == 0) wsum[w] = dacc;
    __syncthreads();
    if (w == 0) {
        int nwarp = blockDim.x >> 5;
        double b = (lane < nwarp) ? wsum[lane] : 0.0;
        #pragma unroll
        for (int off = 4; off > 0; off >>= 1)
            b += __shfl_down_sync(0xffffffffu, b, off);
        if (lane == 0) atomicAdd(&g_sum, b);
    }
}

// ---------------------------------------------------------------------------
// Finalize: tail samples (only if N%4 != 0), scalar output, g_sum self-reset.
// ---------------------------------------------------------------------------
__global__ void final_kernel(const float* __restrict__ pred, int N,
                             const float* __restrict__ means,
                             const float* __restrict__ covs,
                             const int*   __restrict__ indices,
                             float* __restrict__ out)
{
    if (threadIdx.x != 0 || blockIdx.x != 0) return;
    double s = g_sum;
    const int n0 = (N >> 2) << 2;

    int cnt = 0;
    for (int i = 0; i < KC; ++i) if (indices[i] != 0) cnt++;

    if (n0 < N) {
        __shared__ HotP hp;
        for (int j = 0; j < KC; ++j) prep_component(&hp, j, means, covs);
        prep_masks(&hp, indices);
        for (int n = n0; n < N; ++n) {
            for (int i = 0; i < KC; ++i) {
                if (!hp.active[i]) continue;
                const float* base = pred + (size_t)i * D * N;
                float lp[KC];
                for (int j = 0; j < KC; ++j) {
                    float M = hp.cf[j];
                    int t = 0;
                    for (int r = 0; r < D; ++r) {
                        float sr = hp.nb[j][r];
                        for (int c = 0; c <= r; ++c) {
                            sr = fmaf(hp.sL[j][t], base[(size_t)c * N + n], sr);
                            ++t;
                        }
                        M = fmaf(sr, sr, M);
                    }
                    lp[j] = M;
                }
                int tm = hp.tmask[i], em = hp.emask[i];
                float tot = 1e-8f, tll = 0.f;
                for (int j = 0; j < KC; ++j) {
                    float e = __expf(lp[j]);
                    if (!((em >> j) & 1)) tot += e;
                    if ((tm >> j) & 1) tll = lp[j];
                }
                s += (double)(tll - __logf(tot));
            }
        }
    }

    float res = 0.0f;
    if (cnt > 0 && N > 0)
        res = (float)(-s / ((double)N * (double)cnt));
    out[0] = res;

    g_sum = 0.0;   // reset for next graph replay
    __threadfence();
}

// ---------------------------------------------------------------------------
extern "C" void kernel_launch(void* const* d_in, const int* in_sizes, int n_in,
                              void* d_out, int out_size)
{
    const float* pred    = (const float*)d_in[0];  // (K, d, N)
    const float* means   = (const float*)d_in[1];  // (K, d)
    const float* covs    = (const float*)d_in[2];  // (K, d, d)
    const int*   indices = (const int*)d_in[3];    // (K,)

    const int N = in_sizes[0] / (KC * D);
    const int N4 = N >> 2;

    const int threads = 256;
    int blocks = (N4 + threads - 1) / threads;
    if (blocks > 296) blocks = 296;   // <=2 waves at 1 block/SM: inline setup paid ~twice
    if (blocks < 1) blocks = 1;

    lp_kernel<<<blocks, threads>>>(pred, N, means, covs, indices);
    final_kernel<<<1, 32>>>(pred, N, means, covs, indices, (float*)d_out);
}